// round 2
// baseline (speedup 1.0000x reference)
#include <cuda_runtime.h>
#include <cstdint>

// ---------------------------------------------------------------------------
// PhimoeSparseMoeBlock: top-2 MoE with SwiGLU experts.
//   H=4096 hidden, F=6400 ffn, E=8 experts, K=2 top-k, T=512 tokens.
// Inputs (metadata order): x[512,4096], gate_w[8,4096],
//   w1[8,6400,4096], w2[8,4096,6400], w3[8,6400,4096].  Output y[512,4096] f32.
//
// Pipeline:
//   1) zero counts
//   2) router: logits -> softmax -> top2 -> renorm; compact token lists per expert
//   3) GEMM1: h1[slot,f]  = x_gathered @ w1[e]^T
//   4) GEMM2: act[slot,f] = silu(h1) * (x_gathered @ w3[e]^T)   (fused epilogue)
//   5) GEMM3: eout[slot,h] = act @ w2[e]^T
//   6) combine: y[t,h] = w0*eout[slot0,h] + w1*eout[slot1,h]    (deterministic)
// ---------------------------------------------------------------------------

#define NUM_E   8
#define TOKENS  512
#define HDIM    4096
#define FDIM    6400

typedef unsigned long long ull;

// ---- scratch (device globals; no runtime allocation allowed) ----
__device__ int   g_counts[NUM_E];
__device__ int   g_tok [NUM_E * TOKENS];          // token id per (expert, pos)
__device__ int   g_slot[TOKENS * 2];              // per token: e*512+pos for its 2 experts
__device__ float g_wtok[TOKENS * 2];              // per token: renormalized gate weights
__device__ float g_h1 [NUM_E * TOKENS * FDIM];    // 104.9 MB
__device__ float g_act[NUM_E * TOKENS * FDIM];    // 104.9 MB
__device__ float g_eout[NUM_E * TOKENS * HDIM];   //  67.1 MB

// packed f32x2 FMA (Blackwell packed fp32 pipe: 2x the 3-reg FFMA rate)
__device__ __forceinline__ ull ffma2(ull a, ull b, ull c) {
    ull d;
    asm("fma.rn.f32x2 %0, %1, %2, %3;" : "=l"(d) : "l"(a), "l"(b), "l"(c));
    return d;
}
__device__ __forceinline__ void unpack2(ull v, float& lo, float& hi) {
    lo = __uint_as_float((unsigned)(v & 0xffffffffull));
    hi = __uint_as_float((unsigned)(v >> 32));
}

// ---------------------------------------------------------------------------
__global__ void zero_counts_kernel() {
    if (threadIdx.x < NUM_E) g_counts[threadIdx.x] = 0;
}

// Router: one block per token, one warp per expert.
__global__ void router_kernel(const float* __restrict__ x,
                              const float* __restrict__ gw) {
    const int t    = blockIdx.x;
    const int e    = threadIdx.x >> 5;
    const int lane = threadIdx.x & 31;

    const float* xr = x  + (size_t)t * HDIM;
    const float* gr = gw + (size_t)e * HDIM;

    float s = 0.f;
    for (int h = lane * 4; h < HDIM; h += 128) {
        float4 xv = *reinterpret_cast<const float4*>(xr + h);
        float4 gv = *reinterpret_cast<const float4*>(gr + h);
        s += xv.x * gv.x + xv.y * gv.y + xv.z * gv.z + xv.w * gv.w;
    }
    #pragma unroll
    for (int off = 16; off; off >>= 1) s += __shfl_xor_sync(0xffffffffu, s, off);

    __shared__ float logits[NUM_E];
    if (lane == 0) logits[e] = s;
    __syncthreads();

    if (threadIdx.x == 0) {
        float mx = logits[0];
        #pragma unroll
        for (int i = 1; i < NUM_E; ++i) mx = fmaxf(mx, logits[i]);
        float p[NUM_E]; float sum = 0.f;
        #pragma unroll
        for (int i = 0; i < NUM_E; ++i) { p[i] = expf(logits[i] - mx); sum += p[i]; }
        #pragma unroll
        for (int i = 0; i < NUM_E; ++i) p[i] /= sum;

        int i0 = 0;
        #pragma unroll
        for (int i = 1; i < NUM_E; ++i) if (p[i] > p[i0]) i0 = i;
        int i1 = (i0 == 0) ? 1 : 0;
        #pragma unroll
        for (int i = 0; i < NUM_E; ++i) if (i != i0 && p[i] > p[i1]) i1 = i;

        float denom = p[i0] + p[i1];
        float w0 = p[i0] / denom;
        float w1 = p[i1] / denom;

        int pos0 = atomicAdd(&g_counts[i0], 1);
        g_tok[i0 * TOKENS + pos0] = t;
        g_slot[t * 2 + 0] = i0 * TOKENS + pos0;
        g_wtok[t * 2 + 0] = w0;

        int pos1 = atomicAdd(&g_counts[i1], 1);
        g_tok[i1 * TOKENS + pos1] = t;
        g_slot[t * 2 + 1] = i1 * TOKENS + pos1;
        g_wtok[t * 2 + 1] = w1;
    }
}

// ---------------------------------------------------------------------------
// Gather-SGEMM: C[m,n] = sum_k A[m,k] * W[e][n,k]
//   MODE 0: A = x rows gathered via g_tok     -> g_h1
//   MODE 1: A = x rows gathered via g_tok     -> g_act = silu(g_h1) * C
//   MODE 2: A = g_act rows (contiguous)       -> g_eout
// Tiles: BM=BN=128, BK=8, 256 threads, 4x8 f32x2 per thread (8 rows x 8 cols).
// B is stored duplicated in smem as float2{b,b} so the packed-lane FMA needs
// no per-k register packing; A pairs come straight off consecutive m.
// ---------------------------------------------------------------------------
#define BM 128
#define BN 128
#define BK 8

template<int MODE>
__global__ __launch_bounds__(256, 2)
void moe_gemm(const float* __restrict__ A, const float* __restrict__ W) {
    constexpr int KD = (MODE == 2) ? FDIM : HDIM;
    constexpr int ND = (MODE == 2) ? HDIM : FDIM;

    const int e   = blockIdx.z;
    const int cnt = g_counts[e];
    const int m0  = blockIdx.y * BM;
    if (m0 >= cnt) return;
    const int n0  = blockIdx.x * BN;

    __shared__ float  As[BK][BM];
    __shared__ float2 Bs[BK][BN];

    const int tid = threadIdx.x;
    const int lm  = tid >> 1;          // 0..127 : tile row loaded by this thread
    const int lk  = (tid & 1) << 2;    // 0 or 4 : k sub-offset (float4)

    const float* arow;
    if (MODE < 2) {
        int m = m0 + lm;
        int t = g_tok[e * TOKENS + ((m < cnt) ? m : 0)];
        arow = A + (size_t)t * HDIM;
    } else {
        arow = g_act + ((size_t)(e * TOKENS + m0 + lm)) * FDIM;
    }
    const float* brow = W + (size_t)e * ((size_t)ND * KD) + (size_t)(n0 + lm) * KD;

    float4 aReg = *reinterpret_cast<const float4*>(arow + lk);
    float4 bReg = *reinterpret_cast<const float4*>(brow + lk);

    ull acc[4][8];
    #pragma unroll
    for (int i = 0; i < 4; ++i)
        #pragma unroll
        for (int j = 0; j < 8; ++j) acc[i][j] = 0ull;

    const int ty  = tid >> 4;          // 0..15
    const int tx  = tid & 15;          // 0..15
    const int ty8 = ty * 8, tx8 = tx * 8;

    constexpr int NITER = KD / BK;
    for (int kt = 0; kt < NITER; ++kt) {
        As[lk + 0][lm] = aReg.x;
        As[lk + 1][lm] = aReg.y;
        As[lk + 2][lm] = aReg.z;
        As[lk + 3][lm] = aReg.w;
        Bs[lk + 0][lm] = make_float2(bReg.x, bReg.x);
        Bs[lk + 1][lm] = make_float2(bReg.y, bReg.y);
        Bs[lk + 2][lm] = make_float2(bReg.z, bReg.z);
        Bs[lk + 3][lm] = make_float2(bReg.w, bReg.w);
        __syncthreads();

        if (kt + 1 < NITER) {
            int koff = (kt + 1) * BK + lk;
            aReg = *reinterpret_cast<const float4*>(arow + koff);
            bReg = *reinterpret_cast<const float4*>(brow + koff);
        }

        #pragma unroll
        for (int k = 0; k < BK; ++k) {
            ull a2[4], b2[8];
            const ull* ap = reinterpret_cast<const ull*>(&As[k][ty8]);
            #pragma unroll
            for (int i = 0; i < 4; ++i) a2[i] = ap[i];
            const ull* bp = reinterpret_cast<const ull*>(&Bs[k][tx8]);
            #pragma unroll
            for (int j = 0; j < 8; ++j) b2[j] = bp[j];
            #pragma unroll
            for (int i = 0; i < 4; ++i)
                #pragma unroll
                for (int j = 0; j < 8; ++j)
                    acc[i][j] = ffma2(a2[i], b2[j], acc[i][j]);
        }
        __syncthreads();
    }

    // Epilogue: acc[i][j] lanes -> (m = ty8+2i, m+1), n = n0+tx8+j
    #pragma unroll
    for (int i = 0; i < 4; ++i) {
        float rlo[8], rhi[8];
        #pragma unroll
        for (int j = 0; j < 8; ++j) unpack2(acc[i][j], rlo[j], rhi[j]);

        #pragma unroll
        for (int half = 0; half < 2; ++half) {
            const int gm = m0 + ty8 + 2 * i + half;
            if (gm >= cnt) continue;
            const float* r = half ? rhi : rlo;
            const size_t slot = (size_t)(e * TOKENS + gm);

            if (MODE == 0) {
                float* dst = g_h1 + slot * FDIM + n0 + tx8;
                *reinterpret_cast<float4*>(dst)     = make_float4(r[0], r[1], r[2], r[3]);
                *reinterpret_cast<float4*>(dst + 4) = make_float4(r[4], r[5], r[6], r[7]);
            } else if (MODE == 1) {
                const float* h1p = g_h1  + slot * FDIM + n0 + tx8;
                float*       ap_ = g_act + slot * FDIM + n0 + tx8;
                float out[8];
                #pragma unroll
                for (int j = 0; j < 8; ++j) {
                    float h1v = h1p[j];
                    float sil = h1v / (1.0f + expf(-h1v));  // silu
                    out[j] = sil * r[j];
                }
                *reinterpret_cast<float4*>(ap_)     = make_float4(out[0], out[1], out[2], out[3]);
                *reinterpret_cast<float4*>(ap_ + 4) = make_float4(out[4], out[5], out[6], out[7]);
            } else {
                float* dst = g_eout + slot * HDIM + n0 + tx8;
                *reinterpret_cast<float4*>(dst)     = make_float4(r[0], r[1], r[2], r[3]);
                *reinterpret_cast<float4*>(dst + 4) = make_float4(r[4], r[5], r[6], r[7]);
            }
        }
    }
}

// Deterministic per-token combine: y[t,h] = sum_k w_k * eout[slot_k, h]
__global__ void combine_kernel(float* __restrict__ y) {
    int idx = blockIdx.x * blockDim.x + threadIdx.x;
    if (idx >= TOKENS * HDIM) return;
    int t = idx >> 12;          // /4096
    int h = idx & (HDIM - 1);
    int   s0 = g_slot[t * 2 + 0], s1 = g_slot[t * 2 + 1];
    float w0 = g_wtok[t * 2 + 0], w1 = g_wtok[t * 2 + 1];
    y[idx] = w0 * g_eout[(size_t)s0 * HDIM + h] + w1 * g_eout[(size_t)s1 * HDIM + h];
}

// ---------------------------------------------------------------------------
extern "C" void kernel_launch(void* const* d_in, const int* in_sizes, int n_in,
                              void* d_out, int out_size) {
    const float* x  = (const float*)d_in[0];
    const float* gw = (const float*)d_in[1];
    const float* w1 = (const float*)d_in[2];
    const float* w2 = (const float*)d_in[3];
    const float* w3 = (const float*)d_in[4];
    float* y = (float*)d_out;

    zero_counts_kernel<<<1, 32>>>();
    router_kernel<<<TOKENS, 256>>>(x, gw);

    dim3 blk(256);
    dim3 grid1(FDIM / BN, (TOKENS + BM - 1) / BM, NUM_E);  // 50 x 4 x 8
    dim3 grid3(HDIM / BN, (TOKENS + BM - 1) / BM, NUM_E);  // 32 x 4 x 8

    moe_gemm<0><<<grid1, blk>>>(x, w1);
    moe_gemm<1><<<grid1, blk>>>(x, w3);
    moe_gemm<2><<<grid3, blk>>>(nullptr, w2);

    combine_kernel<<<(TOKENS * HDIM + 255) / 256, 256>>>(y);
}

// round 3
// speedup vs baseline: 1.0002x; 1.0002x over previous
#include <cuda_runtime.h>
#include <cstdint>

// ---------------------------------------------------------------------------
// PhimoeSparseMoeBlock: top-2 MoE with SwiGLU experts.
//   H=4096 hidden, F=6400 ffn, E=8 experts, K=2 top-k, T=512 tokens.
// Inputs (metadata order): x[512,4096], gate_w[8,4096],
//   w1[8,6400,4096], w2[8,4096,6400], w3[8,6400,4096].  Output y[512,4096] f32.
//
// Pipeline:
//   1) zero counts
//   2) router: logits -> softmax -> top2 -> renorm; compact token lists per expert
//   3) GEMM1: h1[slot,f]  = x_gathered @ w1[e]^T
//   4) GEMM2: act[slot,f] = silu(h1) * (x_gathered @ w3[e]^T)   (fused epilogue)
//   5) GEMM3: eout[slot,h] = act @ w2[e]^T
//   6) combine: y[t,h] = w0*eout[slot0,h] + w1*eout[slot1,h]    (deterministic)
// ---------------------------------------------------------------------------

#define NUM_E   8
#define TOKENS  512
#define HDIM    4096
#define FDIM    6400

typedef unsigned long long ull;

// ---- scratch (device globals; no runtime allocation allowed) ----
__device__ int   g_counts[NUM_E];
__device__ int   g_tok [NUM_E * TOKENS];          // token id per (expert, pos)
__device__ int   g_slot[TOKENS * 2];              // per token: e*512+pos for its 2 experts
__device__ float g_wtok[TOKENS * 2];              // per token: renormalized gate weights
__device__ float g_h1 [NUM_E * TOKENS * FDIM];    // 104.9 MB
__device__ float g_act[NUM_E * TOKENS * FDIM];    // 104.9 MB
__device__ float g_eout[NUM_E * TOKENS * HDIM];   //  67.1 MB

// packed f32x2 FMA (Blackwell packed fp32 pipe: 2x the 3-reg FFMA rate)
__device__ __forceinline__ ull ffma2(ull a, ull b, ull c) {
    ull d;
    asm("fma.rn.f32x2 %0, %1, %2, %3;" : "=l"(d) : "l"(a), "l"(b), "l"(c));
    return d;
}
__device__ __forceinline__ void unpack2(ull v, float& lo, float& hi) {
    lo = __uint_as_float((unsigned)(v & 0xffffffffull));
    hi = __uint_as_float((unsigned)(v >> 32));
}

// ---------------------------------------------------------------------------
__global__ void zero_counts_kernel() {
    if (threadIdx.x < NUM_E) g_counts[threadIdx.x] = 0;
}

// Router: one block per token, one warp per expert.
__global__ void router_kernel(const float* __restrict__ x,
                              const float* __restrict__ gw) {
    const int t    = blockIdx.x;
    const int e    = threadIdx.x >> 5;
    const int lane = threadIdx.x & 31;

    const float* xr = x  + (size_t)t * HDIM;
    const float* gr = gw + (size_t)e * HDIM;

    float s = 0.f;
    for (int h = lane * 4; h < HDIM; h += 128) {
        float4 xv = *reinterpret_cast<const float4*>(xr + h);
        float4 gv = *reinterpret_cast<const float4*>(gr + h);
        s += xv.x * gv.x + xv.y * gv.y + xv.z * gv.z + xv.w * gv.w;
    }
    #pragma unroll
    for (int off = 16; off; off >>= 1) s += __shfl_xor_sync(0xffffffffu, s, off);

    __shared__ float logits[NUM_E];
    if (lane == 0) logits[e] = s;
    __syncthreads();

    if (threadIdx.x == 0) {
        float mx = logits[0];
        #pragma unroll
        for (int i = 1; i < NUM_E; ++i) mx = fmaxf(mx, logits[i]);
        float p[NUM_E]; float sum = 0.f;
        #pragma unroll
        for (int i = 0; i < NUM_E; ++i) { p[i] = expf(logits[i] - mx); sum += p[i]; }
        #pragma unroll
        for (int i = 0; i < NUM_E; ++i) p[i] /= sum;

        int i0 = 0;
        #pragma unroll
        for (int i = 1; i < NUM_E; ++i) if (p[i] > p[i0]) i0 = i;
        int i1 = (i0 == 0) ? 1 : 0;
        #pragma unroll
        for (int i = 0; i < NUM_E; ++i) if (i != i0 && p[i] > p[i1]) i1 = i;

        float denom = p[i0] + p[i1];
        float w0 = p[i0] / denom;
        float w1 = p[i1] / denom;

        int pos0 = atomicAdd(&g_counts[i0], 1);
        g_tok[i0 * TOKENS + pos0] = t;
        g_slot[t * 2 + 0] = i0 * TOKENS + pos0;
        g_wtok[t * 2 + 0] = w0;

        int pos1 = atomicAdd(&g_counts[i1], 1);
        g_tok[i1 * TOKENS + pos1] = t;
        g_slot[t * 2 + 1] = i1 * TOKENS + pos1;
        g_wtok[t * 2 + 1] = w1;
    }
}

// ---------------------------------------------------------------------------
// Gather-SGEMM: C[m,n] = sum_k A[m,k] * W[e][n,k]
//   MODE 0: A = x rows gathered via g_tok     -> g_h1
//   MODE 1: A = x rows gathered via g_tok     -> g_act = silu(g_h1) * C
//   MODE 2: A = g_act rows (contiguous)       -> g_eout
// Tiles: BM=BN=128, BK=8, 256 threads, 4x8 f32x2 per thread (8 rows x 8 cols).
// B is stored duplicated in smem as float2{b,b} so the packed-lane FMA needs
// no per-k register packing; A pairs come straight off consecutive m.
// ---------------------------------------------------------------------------
#define BM 128
#define BN 128
#define BK 8

template<int MODE>
__global__ __launch_bounds__(256, 2)
void moe_gemm(const float* __restrict__ A, const float* __restrict__ W) {
    constexpr int KD = (MODE == 2) ? FDIM : HDIM;
    constexpr int ND = (MODE == 2) ? HDIM : FDIM;

    const int e   = blockIdx.z;
    const int cnt = g_counts[e];
    const int m0  = blockIdx.y * BM;
    if (m0 >= cnt) return;
    const int n0  = blockIdx.x * BN;

    __shared__ float  As[BK][BM];
    __shared__ float2 Bs[BK][BN];

    const int tid = threadIdx.x;
    const int lm  = tid >> 1;          // 0..127 : tile row loaded by this thread
    const int lk  = (tid & 1) << 2;    // 0 or 4 : k sub-offset (float4)

    const float* arow;
    if (MODE < 2) {
        int m = m0 + lm;
        int t = g_tok[e * TOKENS + ((m < cnt) ? m : 0)];
        arow = A + (size_t)t * HDIM;
    } else {
        arow = g_act + ((size_t)(e * TOKENS + m0 + lm)) * FDIM;
    }
    const float* brow = W + (size_t)e * ((size_t)ND * KD) + (size_t)(n0 + lm) * KD;

    float4 aReg = *reinterpret_cast<const float4*>(arow + lk);
    float4 bReg = *reinterpret_cast<const float4*>(brow + lk);

    ull acc[4][8];
    #pragma unroll
    for (int i = 0; i < 4; ++i)
        #pragma unroll
        for (int j = 0; j < 8; ++j) acc[i][j] = 0ull;

    const int ty  = tid >> 4;          // 0..15
    const int tx  = tid & 15;          // 0..15
    const int ty8 = ty * 8, tx8 = tx * 8;

    constexpr int NITER = KD / BK;
    for (int kt = 0; kt < NITER; ++kt) {
        As[lk + 0][lm] = aReg.x;
        As[lk + 1][lm] = aReg.y;
        As[lk + 2][lm] = aReg.z;
        As[lk + 3][lm] = aReg.w;
        Bs[lk + 0][lm] = make_float2(bReg.x, bReg.x);
        Bs[lk + 1][lm] = make_float2(bReg.y, bReg.y);
        Bs[lk + 2][lm] = make_float2(bReg.z, bReg.z);
        Bs[lk + 3][lm] = make_float2(bReg.w, bReg.w);
        __syncthreads();

        if (kt + 1 < NITER) {
            int koff = (kt + 1) * BK + lk;
            aReg = *reinterpret_cast<const float4*>(arow + koff);
            bReg = *reinterpret_cast<const float4*>(brow + koff);
        }

        #pragma unroll
        for (int k = 0; k < BK; ++k) {
            ull a2[4], b2[8];
            const ull* ap = reinterpret_cast<const ull*>(&As[k][ty8]);
            #pragma unroll
            for (int i = 0; i < 4; ++i) a2[i] = ap[i];
            const ull* bp = reinterpret_cast<const ull*>(&Bs[k][tx8]);
            #pragma unroll
            for (int j = 0; j < 8; ++j) b2[j] = bp[j];
            #pragma unroll
            for (int i = 0; i < 4; ++i)
                #pragma unroll
                for (int j = 0; j < 8; ++j)
                    acc[i][j] = ffma2(a2[i], b2[j], acc[i][j]);
        }
        __syncthreads();
    }

    // Epilogue: acc[i][j] lanes -> (m = ty8+2i, m+1), n = n0+tx8+j
    #pragma unroll
    for (int i = 0; i < 4; ++i) {
        float rlo[8], rhi[8];
        #pragma unroll
        for (int j = 0; j < 8; ++j) unpack2(acc[i][j], rlo[j], rhi[j]);

        #pragma unroll
        for (int half = 0; half < 2; ++half) {
            const int gm = m0 + ty8 + 2 * i + half;
            if (gm >= cnt) continue;
            const float* r = half ? rhi : rlo;
            const size_t slot = (size_t)(e * TOKENS + gm);

            if (MODE == 0) {
                float* dst = g_h1 + slot * FDIM + n0 + tx8;
                *reinterpret_cast<float4*>(dst)     = make_float4(r[0], r[1], r[2], r[3]);
                *reinterpret_cast<float4*>(dst + 4) = make_float4(r[4], r[5], r[6], r[7]);
            } else if (MODE == 1) {
                const float* h1p = g_h1  + slot * FDIM + n0 + tx8;
                float*       ap_ = g_act + slot * FDIM + n0 + tx8;
                float out[8];
                #pragma unroll
                for (int j = 0; j < 8; ++j) {
                    float h1v = h1p[j];
                    float sil = h1v / (1.0f + expf(-h1v));  // silu
                    out[j] = sil * r[j];
                }
                *reinterpret_cast<float4*>(ap_)     = make_float4(out[0], out[1], out[2], out[3]);
                *reinterpret_cast<float4*>(ap_ + 4) = make_float4(out[4], out[5], out[6], out[7]);
            } else {
                float* dst = g_eout + slot * HDIM + n0 + tx8;
                *reinterpret_cast<float4*>(dst)     = make_float4(r[0], r[1], r[2], r[3]);
                *reinterpret_cast<float4*>(dst + 4) = make_float4(r[4], r[5], r[6], r[7]);
            }
        }
    }
}

// Deterministic per-token combine: y[t,h] = sum_k w_k * eout[slot_k, h]
__global__ void combine_kernel(float* __restrict__ y) {
    int idx = blockIdx.x * blockDim.x + threadIdx.x;
    if (idx >= TOKENS * HDIM) return;
    int t = idx >> 12;          // /4096
    int h = idx & (HDIM - 1);
    int   s0 = g_slot[t * 2 + 0], s1 = g_slot[t * 2 + 1];
    float w0 = g_wtok[t * 2 + 0], w1 = g_wtok[t * 2 + 1];
    y[idx] = w0 * g_eout[(size_t)s0 * HDIM + h] + w1 * g_eout[(size_t)s1 * HDIM + h];
}

// ---------------------------------------------------------------------------
extern "C" void kernel_launch(void* const* d_in, const int* in_sizes, int n_in,
                              void* d_out, int out_size) {
    const float* x  = (const float*)d_in[0];
    const float* gw = (const float*)d_in[1];
    const float* w1 = (const float*)d_in[2];
    const float* w2 = (const float*)d_in[3];
    const float* w3 = (const float*)d_in[4];
    float* y = (float*)d_out;

    zero_counts_kernel<<<1, 32>>>();
    router_kernel<<<TOKENS, 256>>>(x, gw);

    dim3 blk(256);
    dim3 grid1(FDIM / BN, (TOKENS + BM - 1) / BM, NUM_E);  // 50 x 4 x 8
    dim3 grid3(HDIM / BN, (TOKENS + BM - 1) / BM, NUM_E);  // 32 x 4 x 8

    moe_gemm<0><<<grid1, blk>>>(x, w1);
    moe_gemm<1><<<grid1, blk>>>(x, w3);
    moe_gemm<2><<<grid3, blk>>>(nullptr, w2);

    combine_kernel<<<(TOKENS * HDIM + 255) / 256, 256>>>(y);
}